// round 1
// baseline (speedup 1.0000x reference)
#include <cuda_runtime.h>
#include <cstdint>

#define HH 28
#define WW 28
#define HWPIX 784
#define NB 128
#define CC 256
#define CW 8          // 256 channels / 32 bits
#define TAPS 9
#define CO_PER_BLOCK 16

// Scratch (no cudaMalloc allowed)
__device__ uint32_t g_xpack[NB * CW * HWPIX];   // [n][word][hw]  ~3.2 MB
__device__ uint32_t g_wpack[CC * TAPS * CW];    // [co][tap][word]
__device__ float    g_scale[CC];
__device__ float    g_bias[CC];

// Pack sign bits of x: bit=1 means negative. Layout [n][word][hw].
__global__ void pack_x_kernel(const float* __restrict__ x) {
    int idx = blockIdx.x * blockDim.x + threadIdx.x;
    if (idx >= NB * CW * HWPIX) return;
    int hw   = idx % HWPIX;
    int word = (idx / HWPIX) % CW;
    int n    = idx / (HWPIX * CW);
    const float* xp = x + (size_t)n * CC * HWPIX + (size_t)word * 32 * HWPIX + hw;
    uint32_t bits = 0;
#pragma unroll
    for (int b = 0; b < 32; b++) {
        float v = xp[(size_t)b * HWPIX];
        bits |= (v < 0.0f ? 1u : 0u) << b;
    }
    g_xpack[idx] = bits;
}

// Pack sign bits of w (OIHW). Layout [co][tap][word].
__global__ void pack_w_kernel(const float* __restrict__ w) {
    int idx = blockIdx.x * blockDim.x + threadIdx.x;
    if (idx >= CC * TAPS * CW) return;
    int word = idx % CW;
    int tap  = (idx / CW) % TAPS;
    int co   = idx / (CW * TAPS);
    uint32_t bits = 0;
#pragma unroll
    for (int b = 0; b < 32; b++) {
        int ci = word * 32 + b;
        float v = w[((size_t)(co * CC + ci)) * TAPS + tap];
        bits |= (v < 0.0f ? 1u : 0u) << b;
    }
    g_wpack[idx] = bits;
}

__global__ void bn_prep_kernel(const float* __restrict__ gamma,
                               const float* __restrict__ beta,
                               const float* __restrict__ mean,
                               const float* __restrict__ var) {
    int c = blockIdx.x * blockDim.x + threadIdx.x;
    if (c < CC) {
        float inv = gamma[c] * rsqrtf(var[c] + 1e-5f);
        g_scale[c] = inv;
        g_bias[c]  = beta[c] - mean[c] * inv;
    }
}

// One block = one image n x 16 output channels. Shared x-bit tile reused 16x.
__global__ __launch_bounds__(256, 2)
void conv_kernel(const float* __restrict__ x, float* __restrict__ out) {
    __shared__ uint32_t s_x[CW][HWPIX];   // [word][hw] -> conflict-free per-lane hw
    int n   = blockIdx.x;
    int co0 = blockIdx.y * CO_PER_BLOCK;
    int tid = threadIdx.x;

    const uint32_t* xp = g_xpack + (size_t)n * CW * HWPIX;
    for (int i = tid; i < CW * HWPIX; i += blockDim.x)
        (&s_x[0][0])[i] = xp[i];
    __syncthreads();

    for (int cg = 0; cg < CO_PER_BLOCK; cg++) {
        int co = co0 + cg;
        uint32_t wr[TAPS * CW];
        const uint32_t* wp = g_wpack + co * TAPS * CW;
#pragma unroll
        for (int i = 0; i < TAPS * CW; i++) wr[i] = __ldg(wp + i);
        float sc = g_scale[co];
        float bi = g_bias[co];

#pragma unroll
        for (int p = 0; p < 4; p++) {
            int pix = tid + p * 256;
            if (pix < HWPIX) {
                int hh = pix / WW;
                int ww = pix - hh * WW;
                int acc = 0, nv = 0;
#pragma unroll
                for (int kh = 0; kh < 3; kh++) {
                    int ih = hh + kh - 1;
                    if ((unsigned)ih < HH) {
#pragma unroll
                        for (int kw = 0; kw < 3; kw++) {
                            int iw = ww + kw - 1;
                            if ((unsigned)iw < WW) {
                                nv++;
                                int ihw = ih * WW + iw;
                                int t = kh * 3 + kw;
#pragma unroll
                                for (int wd = 0; wd < CW; wd++)
                                    acc += __popc(s_x[wd][ihw] ^ wr[t * CW + wd]);
                            }
                        }
                    }
                }
                // per valid tap-word: (+1 matches) - (-1 mismatches) = 32 - 2*popc
                float conv = (float)(256 * nv - 2 * acc);
                float v = fminf(fmaxf(fmaf(conv, sc, bi), -1.0f), 1.0f);
                size_t oidx = ((size_t)n * CC + co) * HWPIX + pix;
                out[oidx] = v + x[oidx];
            }
        }
    }
}

extern "C" void kernel_launch(void* const* d_in, const int* in_sizes, int n_in,
                              void* d_out, int out_size) {
    const float* x     = (const float*)d_in[0];
    const float* w     = (const float*)d_in[1];
    const float* gamma = (const float*)d_in[2];
    const float* beta  = (const float*)d_in[3];
    const float* rmean = (const float*)d_in[4];
    const float* rvar  = (const float*)d_in[5];
    float* out = (float*)d_out;

    {
        int total = NB * CW * HWPIX;
        pack_x_kernel<<<(total + 255) / 256, 256>>>(x);
    }
    {
        int total = CC * TAPS * CW;
        pack_w_kernel<<<(total + 255) / 256, 256>>>(w);
    }
    bn_prep_kernel<<<1, 256>>>(gamma, beta, rmean, rvar);

    dim3 grid(NB, CC / CO_PER_BLOCK);
    conv_kernel<<<grid, 256>>>(x, out);
}